// round 3
// baseline (speedup 1.0000x reference)
#include <cuda_runtime.h>
#include <math.h>

#define B_ 32
#define T_ 512
#define V_ 8000
#define E_ 256
#define U_ 512
#define G4 (4*U_)     // 2048
#define BT (B_*T_)    // 16384
#define HSTRIDE 516   // padded h row stride (bank-conflict-free)

// ---------------- static device scratch (allocation-free) ----------------
__device__ float g_x  [BT*E_];            // embedded input
__device__ float g_xw0[(size_t)BT*G4];    // xW fwd (per layer)
__device__ float g_xw1[(size_t)BT*G4];    // xW bwd (per layer)
__device__ float g_h1 [(size_t)BT*2*U_];  // layer1 output
__device__ float g_h2 [(size_t)BT*2*U_];  // layer2 output
__device__ float g_wr [2][U_*G4];         // reordered Wr per dir
__device__ float g_hs [2][2][B_*U_];      // h state [dir][parity]
__device__ unsigned g_gen[2];             // grid barrier generation, per dir
__device__ unsigned g_cnt[2];             // grid barrier arrive count, per dir

// ---------------- embedding gather ----------------
__global__ void embed_k(const int* __restrict__ tok, const float* __restrict__ emb) {
    int i = blockIdx.x * blockDim.x + threadIdx.x;      // over BT*E_/4 float4s
    int row  = i >> 6;                                   // / (E_/4)
    int col4 = i & 63;
    int t = tok[row];
    reinterpret_cast<float4*>(g_x)[i] =
        reinterpret_cast<const float4*>(emb + (size_t)t * E_)[col4];
}

// ---------------- Wr reorder: [k][g*U+u] -> [k][u*4+g] ----------------
__global__ void reorder_k(const float* __restrict__ rf, const float* __restrict__ rb) {
    int i = blockIdx.x * 256 + threadIdx.x;              // over U_*G4
    int k = i / G4;
    int c = i % G4;
    int u = c >> 2, g = c & 3;
    g_wr[0][i] = rf[(size_t)k * G4 + g * U_ + u];
    g_wr[1][i] = rb[(size_t)k * G4 + g * U_ + u];
}

// ---------------- fp32 tiled GEMM: C[M,N] = A[M,K] @ B[K,N] + bias ----------------
__global__ __launch_bounds__(256)
void sgemm_bias_k(const float* __restrict__ A, const float* __restrict__ B,
                  const float* __restrict__ bias, float* __restrict__ C,
                  int M, int N, int K)
{
    __shared__ float As[8][128];
    __shared__ float Bs[8][128];
    int tid = threadIdx.x;
    int ty = tid >> 4, tx = tid & 15;
    int rowBase = blockIdx.y * 128;
    int colBase = blockIdx.x * 128;

    float acc[8][8];
#pragma unroll
    for (int i = 0; i < 8; i++)
#pragma unroll
        for (int j = 0; j < 8; j++) acc[i][j] = 0.f;

    int arow = tid >> 1;
    int acol = (tid & 1) * 4;
    int brow = tid >> 5;
    int bcol = (tid & 31) * 4;
    const float* Ap = A + (size_t)(rowBase + arow) * K + acol;
    int gcol = colBase + bcol;

    for (int k0 = 0; k0 < K; k0 += 8) {
        float4 av = *(const float4*)(Ap + k0);
        float4 bv = make_float4(0.f, 0.f, 0.f, 0.f);
        if (gcol < N) bv = *(const float4*)(B + (size_t)(k0 + brow) * N + gcol);
        __syncthreads();
        As[acol+0][arow] = av.x; As[acol+1][arow] = av.y;
        As[acol+2][arow] = av.z; As[acol+3][arow] = av.w;
        *(float4*)&Bs[brow][bcol] = bv;
        __syncthreads();
#pragma unroll
        for (int k = 0; k < 8; k++) {
            float4 a0 = *(const float4*)&As[k][ty*4];
            float4 a1 = *(const float4*)&As[k][ty*4 + 64];
            float4 b0 = *(const float4*)&Bs[k][tx*4];
            float4 b1 = *(const float4*)&Bs[k][tx*4 + 64];
            float ar[8] = {a0.x,a0.y,a0.z,a0.w,a1.x,a1.y,a1.z,a1.w};
            float br[8] = {b0.x,b0.y,b0.z,b0.w,b1.x,b1.y,b1.z,b1.w};
#pragma unroll
            for (int i = 0; i < 8; i++)
#pragma unroll
                for (int j = 0; j < 8; j++)
                    acc[i][j] = fmaf(ar[i], br[j], acc[i][j]);
        }
    }
#pragma unroll
    for (int i = 0; i < 8; i++) {
        int r = rowBase + ty*4 + ((i < 4) ? i : (60 + i));
#pragma unroll
        for (int j = 0; j < 8; j++) {
            int c = colBase + tx*4 + ((j < 4) ? j : (60 + j));
            if (c < N) C[(size_t)r * N + c] = acc[i][j] + bias[c];
        }
    }
}

// ---------------- software grid barrier (per direction, 64 CTAs) ----------------
__device__ __forceinline__ void grid_barrier(int dir) {
    __syncthreads();
    if (threadIdx.x == 0) {
        __threadfence();
        volatile unsigned* gen = &g_gen[dir];
        unsigned old = *gen;
        unsigned a = atomicAdd(&g_cnt[dir], 1u);
        if (a == 63u) {
            g_cnt[dir] = 0u;
            __threadfence();
            *gen = old + 1u;
        } else {
            while (*gen == old) { }
        }
        __threadfence();
    }
    __syncthreads();
}

// ---------------- persistent bidirectional LSTM layer ----------------
// grid 128 CTAs: blockIdx.x>>6 = dir, &63 = unit tile (8 units). 128 threads.
// Each thread: 2 batches x 1 unit x 4 gates. Wr slice cached in SMEM once.
__global__ __launch_bounds__(128)
void lstm_layer_k(const float* __restrict__ xwf, const float* __restrict__ xwb,
                  const int* __restrict__ tok, float* __restrict__ y)
{
    extern __shared__ float sm[];
    float* sw  = sm;                 // [512][32]  weight slice (64 KB)
    float* shh = sm + 512*32;        // [32][HSTRIDE] h staging (~64.5 KB)

    int dir = blockIdx.x >> 6;
    int ub  = blockIdx.x & 63;
    int u0  = ub * 8;
    int tid = threadIdx.x;
    int uloc = tid & 7;
    int bp   = tid >> 3;             // 0..15
    int b0 = bp * 2, b1 = b0 + 1;
    int u = u0 + uloc;

    const float* xw = dir ? xwb : xwf;
    const float* wr = g_wr[dir];

    // Load weight slice once: for each k, 32 contiguous floats at u0*4.
    for (int i = tid; i < 512*8; i += 128) {       // 4096 float4s
        int k  = i >> 3;
        int c4 = i & 7;
        ((float4*)sw)[i] = *(const float4*)&wr[(size_t)k * G4 + u0*4 + c4*4];
    }

    // Zero initial h (parity 0) for our units; c/h-prev live in registers.
    for (int i = tid; i < 8*32; i += 128) {
        int bb = i >> 3;
        g_hs[dir][0][bb * U_ + u0 + (i & 7)] = 0.f;
    }
    float c0 = 0.f, c1 = 0.f, hp0 = 0.f, hp1 = 0.f;
    __threadfence();
    grid_barrier(dir);

    for (int s = 0; s < T_; s++) {
        int t = dir ? (T_ - 1 - s) : s;
        const float* hread  = g_hs[dir][s & 1];
        float*       hwrite = g_hs[dir][(s & 1) ^ 1];

        // Stage full h[32][512] into SMEM (coalesced).
        for (int i = tid; i < 32*128; i += 128) {  // 4096 float4s
            int bb = i >> 7;
            int kq = i & 127;
            *(float4*)&shh[bb * HSTRIDE + kq*4] =
                *(const float4*)&hread[bb * U_ + kq*4];
        }
        __syncthreads();

        float acc0[4] = {0.f,0.f,0.f,0.f};
        float acc1[4] = {0.f,0.f,0.f,0.f};
        const float* hr0 = &shh[b0 * HSTRIDE];
        const float* hr1 = &shh[b1 * HSTRIDE];

#pragma unroll 4
        for (int k = 0; k < U_; k += 4) {
            float4 hv0 = *(const float4*)&hr0[k];
            float4 hv1 = *(const float4*)&hr1[k];
            float h0a[4] = {hv0.x, hv0.y, hv0.z, hv0.w};
            float h1a[4] = {hv1.x, hv1.y, hv1.z, hv1.w};
#pragma unroll
            for (int j = 0; j < 4; j++) {
                float4 w = *(const float4*)&sw[(k + j)*32 + uloc*4];
                acc0[0] = fmaf(h0a[j], w.x, acc0[0]);
                acc0[1] = fmaf(h0a[j], w.y, acc0[1]);
                acc0[2] = fmaf(h0a[j], w.z, acc0[2]);
                acc0[3] = fmaf(h0a[j], w.w, acc0[3]);
                acc1[0] = fmaf(h1a[j], w.x, acc1[0]);
                acc1[1] = fmaf(h1a[j], w.y, acc1[1]);
                acc1[2] = fmaf(h1a[j], w.z, acc1[2]);
                acc1[3] = fmaf(h1a[j], w.w, acc1[3]);
            }
        }

        // ---- gates, state update, masked carry (batch b0) ----
        {
            size_t base = ((size_t)b0 * T_ + t) * G4;
            float zi = acc0[0] + xw[base + 0*U_ + u];
            float zf = acc0[1] + xw[base + 1*U_ + u];
            float zg = acc0[2] + xw[base + 2*U_ + u];
            float zo = acc0[3] + xw[base + 3*U_ + u];
            float ig = 1.f / (1.f + expf(-zi));
            float fg = 1.f / (1.f + expf(-zf));
            float gg = tanhf(zg);
            float og = 1.f / (1.f + expf(-zo));
            float cn = fg * c0 + ig * gg;
            float hn = og * tanhf(cn);
            if (tok[b0 * T_ + t] != 0) { c0 = cn; hp0 = hn; }
            hwrite[b0 * U_ + u] = hp0;
            y[((size_t)b0 * T_ + t) * (2*U_) + dir * U_ + u] = hp0;
        }
        // ---- batch b1 ----
        {
            size_t base = ((size_t)b1 * T_ + t) * G4;
            float zi = acc1[0] + xw[base + 0*U_ + u];
            float zf = acc1[1] + xw[base + 1*U_ + u];
            float zg = acc1[2] + xw[base + 2*U_ + u];
            float zo = acc1[3] + xw[base + 3*U_ + u];
            float ig = 1.f / (1.f + expf(-zi));
            float fg = 1.f / (1.f + expf(-zf));
            float gg = tanhf(zg);
            float og = 1.f / (1.f + expf(-zo));
            float cn = fg * c1 + ig * gg;
            float hn = og * tanhf(cn);
            if (tok[b1 * T_ + t] != 0) { c1 = cn; hp1 = hn; }
            hwrite[b1 * U_ + u] = hp1;
            y[((size_t)b1 * T_ + t) * (2*U_) + dir * U_ + u] = hp1;
        }

        __threadfence();
        grid_barrier(dir);
    }
}

// ---------------- host ----------------
extern "C" void kernel_launch(void* const* d_in, const int* in_sizes, int n_in,
                              void* d_out, int out_size)
{
    const int*   tokens = (const int*)  d_in[0];
    const float* emb    = (const float*)d_in[1];
    const float* k1f    = (const float*)d_in[2];
    const float* r1f    = (const float*)d_in[3];
    const float* b1f    = (const float*)d_in[4];
    const float* k1b    = (const float*)d_in[5];
    const float* r1b    = (const float*)d_in[6];
    const float* b1b    = (const float*)d_in[7];
    const float* k2f    = (const float*)d_in[8];
    const float* r2f    = (const float*)d_in[9];
    const float* b2f    = (const float*)d_in[10];
    const float* k2b    = (const float*)d_in[11];
    const float* r2b    = (const float*)d_in[12];
    const float* b2b    = (const float*)d_in[13];
    const float* wd     = (const float*)d_in[14];
    const float* bd     = (const float*)d_in[15];
    float* out = (float*)d_out;

    static float *px = nullptr, *pxw0, *pxw1, *ph1, *ph2;
    if (!px) {   // one-time setup during the correctness call (not during capture)
        cudaGetSymbolAddress((void**)&px,   g_x);
        cudaGetSymbolAddress((void**)&pxw0, g_xw0);
        cudaGetSymbolAddress((void**)&pxw1, g_xw1);
        cudaGetSymbolAddress((void**)&ph1,  g_h1);
        cudaGetSymbolAddress((void**)&ph2,  g_h2);
        cudaFuncSetAttribute(lstm_layer_k,
                             cudaFuncAttributeMaxDynamicSharedMemorySize,
                             (512*32 + 32*HSTRIDE) * sizeof(float));
    }
    const int lstm_smem = (512*32 + 32*HSTRIDE) * sizeof(float);

    embed_k<<<(BT*E_/4)/256, 256>>>(tokens, emb);

    // ---- layer 1 ----
    reorder_k<<<(U_*G4)/256, 256>>>(r1f, r1b);
    sgemm_bias_k<<<dim3(G4/128, BT/128), 256>>>(px, k1f, b1f, pxw0, BT, G4, E_);
    sgemm_bias_k<<<dim3(G4/128, BT/128), 256>>>(px, k1b, b1b, pxw1, BT, G4, E_);
    lstm_layer_k<<<128, 128, lstm_smem>>>(pxw0, pxw1, tokens, ph1);

    // ---- layer 2 ----
    reorder_k<<<(U_*G4)/256, 256>>>(r2f, r2b);
    sgemm_bias_k<<<dim3(G4/128, BT/128), 256>>>(ph1, k2f, b2f, pxw0, BT, G4, 2*U_);
    sgemm_bias_k<<<dim3(G4/128, BT/128), 256>>>(ph1, k2b, b2b, pxw1, BT, G4, 2*U_);
    lstm_layer_k<<<128, 128, lstm_smem>>>(pxw0, pxw1, tokens, ph2);

    // ---- output projection ----
    sgemm_bias_k<<<dim3((V_ + 127)/128, BT/128), 256>>>(ph2, wd, bd, out, BT, V_, 2*U_);
}

// round 6
// speedup vs baseline: 1.2358x; 1.2358x over previous
#include <cuda_runtime.h>
#include <math.h>
#include <stdint.h>

#define B_ 32
#define T_ 512
#define V_ 8000
#define E_ 256
#define U_ 512
#define G4 (4*U_)     // 2048
#define BT (B_*T_)    // 16384
#define HSTRIDE 516
#define VPAD 8064     // V padded to multiple of 128

#define BM 128
#define BN 128
#define BK 16
#define PADK 20       // smem row stride (floats); conflict-free for frag loads

// ---------------- static device scratch ----------------
__device__ float g_x  [BT*E_];
__device__ float g_xw0[(size_t)BT*G4];
__device__ float g_xw1[(size_t)BT*G4];
__device__ float g_h1 [(size_t)BT*2*U_];
__device__ float g_h2 [(size_t)BT*2*U_];
__device__ float g_wr [2][U_*G4];
__device__ float g_hs [2][2][B_*U_];
__device__ float g_wdT[(size_t)VPAD*2*U_];
__device__ float g_kT [2][(size_t)G4*2*U_];
__device__ unsigned g_gen[2];
__device__ unsigned g_cnt[2];

// ---------------- helpers ----------------
__device__ __forceinline__ uint32_t smem_u32(const void* p) {
    uint32_t a;
    asm("{ .reg .u64 t; cvta.to.shared.u64 t, %1; cvt.u32.u64 %0, t; }" : "=r"(a) : "l"(p));
    return a;
}
__device__ __forceinline__ float rna_tf32f(float x) {
    uint32_t r; asm("cvt.rna.tf32.f32 %0, %1;" : "=r"(r) : "f"(x));
    return __uint_as_float(r);
}
__device__ __forceinline__ void cp16(uint32_t dst, const void* src) {
    asm volatile("cp.async.ca.shared.global [%0], [%1], 16;" :: "r"(dst), "l"(src));
}
__device__ __forceinline__ void cp_commit() {
    asm volatile("cp.async.commit_group;" ::: "memory");
}
template <int N>
__device__ __forceinline__ void cp_wait() {
    asm volatile("cp.async.wait_group %0;" :: "n"(N) : "memory");
}
__device__ __forceinline__ void mma_tf32(float c[4], const uint32_t a[4], const uint32_t b[2]) {
    asm volatile(
        "mma.sync.aligned.m16n8k8.row.col.f32.tf32.tf32.f32 "
        "{%0,%1,%2,%3}, {%4,%5,%6,%7}, {%8,%9}, {%0,%1,%2,%3};"
        : "+f"(c[0]), "+f"(c[1]), "+f"(c[2]), "+f"(c[3])
        : "r"(a[0]), "r"(a[1]), "r"(a[2]), "r"(a[3]), "r"(b[0]), "r"(b[1]));
}

// ---------------- embedding gather (round to tf32 for GEMM A input) ----------------
__global__ void embed_k(const int* __restrict__ tok, const float* __restrict__ emb) {
    int i = blockIdx.x * blockDim.x + threadIdx.x;
    int row  = i >> 6;
    int col4 = i & 63;
    int t = tok[row];
    float4 v = reinterpret_cast<const float4*>(emb + (size_t)t * E_)[col4];
    v.x = rna_tf32f(v.x); v.y = rna_tf32f(v.y);
    v.z = rna_tf32f(v.z); v.w = rna_tf32f(v.w);
    reinterpret_cast<float4*>(g_x)[i] = v;
}

// ---------------- Wr reorder: [k][g*U+u] -> [k][u*4+g] ----------------
__global__ void reorder_k(const float* __restrict__ rf, const float* __restrict__ rb) {
    int i = blockIdx.x * 256 + threadIdx.x;
    int k = i / G4;
    int c = i % G4;
    int u = c >> 2, g = c & 3;
    g_wr[0][i] = rf[(size_t)k * G4 + g * U_ + u];
    g_wr[1][i] = rb[(size_t)k * G4 + g * U_ + u];
}

// ---------------- transpose + tf32-round: in[K][N] -> out[Npad][K] ----------------
__global__ void transpose_round_k(const float* __restrict__ in, float* __restrict__ out,
                                  int K, int N) {
    __shared__ float t[32][33];
    int n0 = blockIdx.x * 32, k0 = blockIdx.y * 32;
    int tx = threadIdx.x, ty = threadIdx.y;      // (32, 8)
#pragma unroll
    for (int j = 0; j < 4; j++) {
        int k = k0 + ty + j * 8;
        int n = n0 + tx;
        float v = (n < N) ? in[(size_t)k * N + n] : 0.f;
        t[ty + j * 8][tx] = rna_tf32f(v);
    }
    __syncthreads();
#pragma unroll
    for (int j = 0; j < 4; j++)
        out[(size_t)(n0 + ty + j * 8) * K + k0 + tx] = t[tx][ty + j * 8];
}

// ---------------- tf32 mma.sync GEMM: C[M,N] = A[M,K] @ Bt[N,K]^T + bias ----------------
// grid (Npad/128, M/128), 256 threads (8 warps, 4x2), warp tile 32x64.
__global__ __launch_bounds__(256)
void tf32_gemm_k(const float* __restrict__ A, const float* __restrict__ Bt,
                 const float* __restrict__ bias, float* __restrict__ C,
                 int N, int K)
{
    __shared__ float s_as[2][BM*PADK];
    __shared__ float s_bs[2][BN*PADK];

    int tid = threadIdx.x;
    int wid = tid >> 5, lane = tid & 31;
    int wm = wid >> 1, wn = wid & 1;
    int gid = lane >> 2, tg = lane & 3;
    int rowBase = blockIdx.y * BM, colBase = blockIdx.x * BN;

    float c[2][8][4];
#pragma unroll
    for (int i = 0; i < 2; i++)
#pragma unroll
        for (int j = 0; j < 8; j++)
#pragma unroll
            for (int q = 0; q < 4; q++) c[i][j][q] = 0.f;

    const int nc = K / BK;

    auto stage = [&](int chunk, int buf) {
        int k0 = chunk * BK;
#pragma unroll
        for (int it = 0; it < 2; it++) {
            int idx = it * 256 + tid;
            int row = idx >> 2, c4 = idx & 3;
            cp16(smem_u32(&s_as[buf][row*PADK + c4*4]),
                 A + (size_t)(rowBase + row) * K + k0 + c4*4);
            cp16(smem_u32(&s_bs[buf][row*PADK + c4*4]),
                 Bt + (size_t)(colBase + row) * K + k0 + c4*4);
        }
        cp_commit();
    };

    stage(0, 0);

    for (int i = 0; i < nc; i++) {
        int buf = i & 1;
        if (i + 1 < nc) {
            stage(i + 1, buf ^ 1);
            cp_wait<1>();
        } else {
            cp_wait<0>();
        }
        __syncthreads();

        const uint32_t* Au = (const uint32_t*)s_as[buf];
        const uint32_t* Bu = (const uint32_t*)s_bs[buf];
#pragma unroll
        for (int k8 = 0; k8 < BK; k8 += 8) {
            uint32_t af[2][4];
#pragma unroll
            for (int ma = 0; ma < 2; ma++) {
                int base = (wm*32 + ma*16 + gid)*PADK + k8 + tg;
                af[ma][0] = Au[base];
                af[ma][1] = Au[base + 8*PADK];
                af[ma][2] = Au[base + 4];
                af[ma][3] = Au[base + 8*PADK + 4];
            }
            uint32_t bf[8][2];
#pragma unroll
            for (int nb = 0; nb < 8; nb++) {
                int base = (wn*64 + nb*8 + gid)*PADK + k8 + tg;
                bf[nb][0] = Bu[base];
                bf[nb][1] = Bu[base + 4];
            }
#pragma unroll
            for (int ma = 0; ma < 2; ma++)
#pragma unroll
                for (int nb = 0; nb < 8; nb++)
                    mma_tf32(c[ma][nb], af[ma], bf[nb]);
        }
        __syncthreads();
    }

    // ---- epilogue: direct stores (+bias), 32B sector per 4-lane group ----
#pragma unroll
    for (int ma = 0; ma < 2; ma++) {
        int r0 = rowBase + wm*32 + ma*16 + gid;
#pragma unroll
        for (int nb = 0; nb < 8; nb++) {
            int col = colBase + wn*64 + nb*8 + tg*2;
            if (col < N) {
                float b0 = bias[col], b1 = bias[col + 1];
                *(float2*)&C[(size_t)r0 * N + col] =
                    make_float2(c[ma][nb][0] + b0, c[ma][nb][1] + b1);
                *(float2*)&C[(size_t)(r0 + 8) * N + col] =
                    make_float2(c[ma][nb][2] + b0, c[ma][nb][3] + b1);
            }
        }
    }
}

// ---------------- software grid barrier ----------------
__device__ __forceinline__ void grid_barrier(int dir) {
    __syncthreads();
    if (threadIdx.x == 0) {
        __threadfence();
        volatile unsigned* gen = &g_gen[dir];
        unsigned old = *gen;
        unsigned a = atomicAdd(&g_cnt[dir], 1u);
        if (a == 63u) {
            g_cnt[dir] = 0u;
            __threadfence();
            *gen = old + 1u;
        } else {
            while (*gen == old) { }
        }
        __threadfence();
    }
    __syncthreads();
}

// ---------------- persistent bidirectional LSTM layer ----------------
__global__ __launch_bounds__(128)
void lstm_layer_k(const float* __restrict__ xwf, const float* __restrict__ xwb,
                  const int* __restrict__ tok, float* __restrict__ y)
{
    extern __shared__ float sm[];
    float* sw  = sm;
    float* shh = sm + 512*32;

    int dir = blockIdx.x >> 6;
    int ub  = blockIdx.x & 63;
    int u0  = ub * 8;
    int tid = threadIdx.x;
    int uloc = tid & 7;
    int bp   = tid >> 3;
    int b0 = bp * 2, b1 = b0 + 1;
    int u = u0 + uloc;

    const float* xw = dir ? xwb : xwf;
    const float* wr = g_wr[dir];

    for (int i = tid; i < 512*8; i += 128) {
        int k  = i >> 3;
        int c4 = i & 7;
        ((float4*)sw)[i] = *(const float4*)&wr[(size_t)k * G4 + u0*4 + c4*4];
    }
    for (int i = tid; i < 8*32; i += 128) {
        int bb = i >> 3;
        g_hs[dir][0][bb * U_ + u0 + (i & 7)] = 0.f;
    }
    float c0 = 0.f, c1 = 0.f, hp0 = 0.f, hp1 = 0.f;
    __threadfence();
    grid_barrier(dir);

    for (int s = 0; s < T_; s++) {
        int t = dir ? (T_ - 1 - s) : s;
        const float* hread  = g_hs[dir][s & 1];
        float*       hwrite = g_hs[dir][(s & 1) ^ 1];

        for (int i = tid; i < 32*128; i += 128) {
            int bb = i >> 7;
            int kq = i & 127;
            *(float4*)&shh[bb * HSTRIDE + kq*4] =
                *(const float4*)&hread[bb * U_ + kq*4];
        }
        __syncthreads();

        float acc0[4] = {0.f,0.f,0.f,0.f};
        float acc1[4] = {0.f,0.f,0.f,0.f};
        const float* hr0 = &shh[b0 * HSTRIDE];
        const float* hr1 = &shh[b1 * HSTRIDE];

#pragma unroll 4
        for (int k = 0; k < U_; k += 4) {
            float4 hv0 = *(const float4*)&hr0[k];
            float4 hv1 = *(const float4*)&hr1[k];
            float h0a[4] = {hv0.x, hv0.y, hv0.z, hv0.w};
            float h1a[4] = {hv1.x, hv1.y, hv1.z, hv1.w};
#pragma unroll
            for (int j = 0; j < 4; j++) {
                float4 w = *(const float4*)&sw[(k + j)*32 + uloc*4];
                acc0[0] = fmaf(h0a[j], w.x, acc0[0]);
                acc0[1] = fmaf(h0a[j], w.y, acc0[1]);
                acc0[2] = fmaf(h0a[j], w.z, acc0[2]);
                acc0[3] = fmaf(h0a[j], w.w, acc0[3]);
                acc1[0] = fmaf(h1a[j], w.x, acc1[0]);
                acc1[1] = fmaf(h1a[j], w.y, acc1[1]);
                acc1[2] = fmaf(h1a[j], w.z, acc1[2]);
                acc1[3] = fmaf(h1a[j], w.w, acc1[3]);
            }
        }

        {
            size_t base = ((size_t)b0 * T_ + t) * G4;
            float zi = acc0[0] + xw[base + 0*U_ + u];
            float zf = acc0[1] + xw[base + 1*U_ + u];
            float zg = acc0[2] + xw[base + 2*U_ + u];
            float zo = acc0[3] + xw[base + 3*U_ + u];
            float ig = 1.f / (1.f + expf(-zi));
            float fg = 1.f / (1.f + expf(-zf));
            float gg = tanhf(zg);
            float og = 1.f / (1.f + expf(-zo));
            float cn = fg * c0 + ig * gg;
            float hn = og * tanhf(cn);
            if (tok[b0 * T_ + t] != 0) { c0 = cn; hp0 = hn; }
            hwrite[b0 * U_ + u] = hp0;
            y[((size_t)b0 * T_ + t) * (2*U_) + dir * U_ + u] = rna_tf32f(hp0);
        }
        {
            size_t base = ((size_t)b1 * T_ + t) * G4;
            float zi = acc1[0] + xw[base + 0*U_ + u];
            float zf = acc1[1] + xw[base + 1*U_ + u];
            float zg = acc1[2] + xw[base + 2*U_ + u];
            float zo = acc1[3] + xw[base + 3*U_ + u];
            float ig = 1.f / (1.f + expf(-zi));
            float fg = 1.f / (1.f + expf(-zf));
            float gg = tanhf(zg);
            float og = 1.f / (1.f + expf(-zo));
            float cn = fg * c1 + ig * gg;
            float hn = og * tanhf(cn);
            if (tok[b1 * T_ + t] != 0) { c1 = cn; hp1 = hn; }
            hwrite[b1 * U_ + u] = hp1;
            y[((size_t)b1 * T_ + t) * (2*U_) + dir * U_ + u] = rna_tf32f(hp1);
        }

        __threadfence();
        grid_barrier(dir);
    }
}

// ---------------- host ----------------
extern "C" void kernel_launch(void* const* d_in, const int* in_sizes, int n_in,
                              void* d_out, int out_size)
{
    const int*   tokens = (const int*)  d_in[0];
    const float* emb    = (const float*)d_in[1];
    const float* k1f    = (const float*)d_in[2];
    const float* r1f    = (const float*)d_in[3];
    const float* b1f    = (const float*)d_in[4];
    const float* k1b    = (const float*)d_in[5];
    const float* r1b    = (const float*)d_in[6];
    const float* b1b    = (const float*)d_in[7];
    const float* k2f    = (const float*)d_in[8];
    const float* r2f    = (const float*)d_in[9];
    const float* b2f    = (const float*)d_in[10];
    const float* k2b    = (const float*)d_in[11];
    const float* r2b    = (const float*)d_in[12];
    const float* b2b    = (const float*)d_in[13];
    const float* wd     = (const float*)d_in[14];
    const float* bd     = (const float*)d_in[15];
    float* out = (float*)d_out;

    static float *px = nullptr, *pxw0, *pxw1, *ph1, *ph2, *pwdT, *pkT0, *pkT1;
    if (!px) {
        cudaGetSymbolAddress((void**)&px,   g_x);
        cudaGetSymbolAddress((void**)&pxw0, g_xw0);
        cudaGetSymbolAddress((void**)&pxw1, g_xw1);
        cudaGetSymbolAddress((void**)&ph1,  g_h1);
        cudaGetSymbolAddress((void**)&ph2,  g_h2);
        cudaGetSymbolAddress((void**)&pwdT, g_wdT);
        cudaGetSymbolAddress((void**)&pkT0, g_kT);
        pkT1 = pkT0 + (size_t)G4 * 2 * U_;
        cudaFuncSetAttribute(lstm_layer_k,
                             cudaFuncAttributeMaxDynamicSharedMemorySize,
                             (512*32 + 32*HSTRIDE) * sizeof(float));
    }
    const int lstm_smem = (512*32 + 32*HSTRIDE) * sizeof(float);

    embed_k<<<(BT*E_/4)/256, 256>>>(tokens, emb);

    // ---- layer 1: xW GEMMs (K=256, N=2048) ----
    reorder_k<<<(U_*G4)/256, 256>>>(r1f, r1b);
    transpose_round_k<<<dim3(G4/32, E_/32), dim3(32,8)>>>(k1f, pkT0, E_, G4);
    transpose_round_k<<<dim3(G4/32, E_/32), dim3(32,8)>>>(k1b, pkT1, E_, G4);
    tf32_gemm_k<<<dim3(G4/128, BT/128), 256>>>(px, pkT0, b1f, pxw0, G4, E_);
    tf32_gemm_k<<<dim3(G4/128, BT/128), 256>>>(px, pkT1, b1b, pxw1, G4, E_);
    lstm_layer_k<<<128, 128, lstm_smem>>>(pxw0, pxw1, tokens, ph1);

    // ---- layer 2: xW GEMMs (K=1024, N=2048) ----
    reorder_k<<<(U_*G4)/256, 256>>>(r2f, r2b);
    transpose_round_k<<<dim3(G4/32, (2*U_)/32), dim3(32,8)>>>(k2f, pkT0, 2*U_, G4);
    transpose_round_k<<<dim3(G4/32, (2*U_)/32), dim3(32,8)>>>(k2b, pkT1, 2*U_, G4);
    tf32_gemm_k<<<dim3(G4/128, BT/128), 256>>>(ph1, pkT0, b2f, pxw0, G4, 2*U_);
    tf32_gemm_k<<<dim3(G4/128, BT/128), 256>>>(ph1, pkT1, b2b, pxw1, G4, 2*U_);
    lstm_layer_k<<<128, 128, lstm_smem>>>(pxw0, pxw1, tokens, ph2);

    // ---- output projection (K=1024, N=8000 padded to 8064) ----
    transpose_round_k<<<dim3(VPAD/32, (2*U_)/32), dim3(32,8)>>>(wd, pwdT, 2*U_, V_);
    tf32_gemm_k<<<dim3(VPAD/128, BT/128), 256>>>(ph2, pwdT, bd, out, V_, 2*U_);
}